// round 11
// baseline (speedup 1.0000x reference)
#include <cuda_runtime.h>
#include <math.h>

#define NEG_INF (-1e10f)
#define BATCH 4
#define NN 1024
#define DD 32
#define WPR 32   // u32 words per bitset row
#define FULL 0xFFFFFFFFu

#define PACK_BLOCKS (BATCH * NN / 8)        // 512, warp per row
#define GMAX_BLOCKS (BATCH * 32 / 8)        // 16,  warp per (b,group)

// 512KB bitset scratch + 16KB group-max scratch (device globals: allowed)
__device__ unsigned g_bits[BATCH * NN * WPR];
__device__ float    g_gm[BATCH * 32 * DD];   // [b][group][d]

// ---------------------------------------------------------------------------
// Fused: pack edges -> bitset rows (blocks [0,512)) + group maxes (blocks
// [512,528)). Pack: one warp per row, uint4 loads (MLP=8), shfl-OR reduce.
// launch_bounds(256,2): 128-reg budget so the 8 uint4 loads can front-batch.
// ---------------------------------------------------------------------------
__global__ __launch_bounds__(256, 2)
void pack_gmax_kernel(const int* __restrict__ edges,
                      const float* __restrict__ feat) {
    const int lane = threadIdx.x & 31;
    const int warp = threadIdx.x >> 5;

    if (blockIdx.x < PACK_BLOCKS) {
        const int rowId = blockIdx.x * 8 + warp;            // 0..4095
        const uint4* row = (const uint4*)(edges + (size_t)rowId * NN);
        // Front-batch all 8 uint4 loads (needs ~32 regs of data alone).
        uint4 v[8];
        #pragma unroll
        for (int i = 0; i < 8; ++i) v[i] = row[i * 32 + lane];

        unsigned myword = 0u;
        #pragma unroll
        for (int i = 0; i < 8; ++i) {
            unsigned nib = (unsigned)(v[i].x != 0)
                         | ((unsigned)(v[i].y != 0) << 1)
                         | ((unsigned)(v[i].z != 0) << 2)
                         | ((unsigned)(v[i].w != 0) << 3);
            unsigned val = nib << ((lane & 7) * 4);
            // OR-butterfly within each 8-lane group -> word (i*4 + lane>>3)
            val |= __shfl_xor_sync(FULL, val, 1);
            val |= __shfl_xor_sync(FULL, val, 2);
            val |= __shfl_xor_sync(FULL, val, 4);
            // lane 4i+g grabs word g of this iteration (held by lane g*8)
            unsigned w = __shfl_sync(FULL, val, (lane & 3) << 3);
            if ((lane >> 2) == i) myword = w;
        }
        g_bits[rowId * WPR + lane] = myword;                // coalesced
    } else {
        // group maxes: warp per (b,group); idx = b*32+g in [0,128)
        const int idx = (blockIdx.x - PACK_BLOCKS) * 8 + warp;
        const float* f = feat + (size_t)idx * 32 * DD + lane;
        float m0 = f[0], m1 = f[DD], m2 = f[2 * DD], m3 = f[3 * DD];
        #pragma unroll
        for (int j = 4; j < 32; j += 4) {
            m0 = fmaxf(m0, f[j * DD]);
            m1 = fmaxf(m1, f[(j + 1) * DD]);
            m2 = fmaxf(m2, f[(j + 2) * DD]);
            m3 = fmaxf(m3, f[(j + 3) * DD]);
        }
        g_gm[idx * DD + lane] = fmaxf(fmaxf(m0, m1), fmaxf(m2, m3));
    }
}

// ---------------------------------------------------------------------------
// E2-row construction: one full word of neighbors per round. Lane t gets the
// (t+1)-th set-bit index via HW __fns (idempotent duplicate past popcount:
// re-ORing a row is a no-op -> exact). All 32 indices are shfl-gathered into
// a fully-unrolled register array, then 32 UNCONDITIONAL LDGs issue
// back-to-back (true MLP~32; 128-reg budget from launch_bounds(256,2)).
// Exact saturation early-exit; exact general pooling fallback.
// Grid: (NN/8, BATCH), 256 threads, one warp per output row.
// ---------------------------------------------------------------------------
__global__ __launch_bounds__(256, 2)
void pool_kernel(const float* __restrict__ feat, float* __restrict__ out) {
    __shared__ float sgm[32 * DD];   // 4KB: this batch's group maxes

    const int b    = blockIdx.y;
    const int tid  = threadIdx.x;
    const int lane = tid & 31;
    const int warp = tid >> 5;
    const int i    = blockIdx.x * 8 + warp;        // output row

    const unsigned* __restrict__ bb = g_bits + (size_t)b * NN * WPR;
    const float* fb = feat + (size_t)b * NN * DD;

    // Issue the row-of-E load before the smem stage so it overlaps.
    const unsigned rw = bb[i * WPR + lane];        // row i of E

    ((float4*)sgm)[tid] = ((const float4*)(g_gm + b * 32 * DD))[tid];
    __syncthreads();

    // --- build E2 row i: acc (lane holds word `lane`) ---
    unsigned acc = 0u;
    bool sat = false;                              // warp-uniform
    for (int w = 0; w < 32 && !sat; ++w) {
        const unsigned m = __shfl_sync(FULL, rw, w);   // warp-uniform word
        if (!m) continue;
        const int base = w << 5;
        const int fallback = base + __ffs(m) - 1;      // a real neighbor

        // Lane t: index of (t+1)-th set bit, else idempotent duplicate.
        const unsigned pos = __fns(m, 0, lane + 1);    // 0xFFFFFFFF if none
        const int myidx = (pos < 32u) ? (base + (int)pos) : fallback;

        // Gather all 32 indices into registers (fully unrolled -> no local).
        int kreg[32];
        #pragma unroll
        for (int t = 0; t < 32; ++t)
            kreg[t] = __shfl_sync(FULL, myidx, t);

        // 32 unconditional, independent LDGs; 8 accumulators.
        unsigned v[8];
        #pragma unroll
        for (int t = 0; t < 8; ++t) v[t] = 0u;
        #pragma unroll
        for (int t = 0; t < 32; ++t)
            v[t & 7] |= bb[(kreg[t] << 5) + lane];

        acc |= ((v[0] | v[1]) | (v[2] | v[3])) |
               ((v[4] | v[5]) | (v[6] | v[7]));
        // Exact: once all 1024 bits set, further ORs are no-ops.
        sat = __all_sync(FULL, acc == FULL);
    }

    float best;
    if (sat) {
        // Everything visible: max over all group maxes (batch max).
        best = sgm[lane];
        #pragma unroll
        for (int g = 1; g < 32; ++g) best = fmaxf(best, sgm[(g << 5) + lane]);
    } else {
        best = -INFINITY;
        for (int g = 0; g < 32; ++g) {
            const unsigned mg = __shfl_sync(FULL, acc, g);   // uniform
            const float gmv = sgm[(g << 5) + lane];
            float v;
            if (mg == FULL) {
                v = gmv;                        // whole group visible
            } else if (mg == 0u) {
                v = gmv + NEG_INF;              // whole group masked (exact)
            } else {
                v = -INFINITY;                  // mixed group: per-element
                for (int jj = 0; jj < 32; ++jj) {
                    float fv = fb[(size_t)((g << 5) + jj) * DD + lane];
                    v = fmaxf(v, fv + (((mg >> jj) & 1u) ? 0.0f : NEG_INF));
                }
            }
            best = fmaxf(best, v);
        }
    }
    out[((size_t)b * NN + i) * DD + lane] = best;   // coalesced 128B/warp
}

// ---------------------------------------------------------------------------
extern "C" void kernel_launch(void* const* d_in, const int* in_sizes, int n_in,
                              void* d_out, int out_size) {
    const float* feat;
    const int*   edges;
    if (in_sizes[0] == BATCH * NN * DD) {
        feat  = (const float*)d_in[0];
        edges = (const int*)d_in[1];
    } else {
        feat  = (const float*)d_in[1];
        edges = (const int*)d_in[0];
    }

    pack_gmax_kernel<<<PACK_BLOCKS + GMAX_BLOCKS, 256>>>(edges, feat);
    pool_kernel<<<dim3(NN / 8, BATCH), 256>>>(feat, (float*)d_out);

    (void)n_in; (void)out_size;
}